// round 2
// baseline (speedup 1.0000x reference)
#include <cuda_runtime.h>
#include <cuda_bf16.h>
#include <cstdint>
#include <math.h>

// Problem constants
constexpr int BS = 16, C = 64, H = 128, W = 128;
constexpr int HW = H * W;           // 16384
constexpr int NC = 80;
constexpr int TOPK = 128;
constexpr int NKEY = TOPK + NC;     // 208

// Scratch (device globals; no allocation allowed)
__device__ int   g_peak[BS * NC];
__device__ float g_cmask[BS * NC];
__device__ float g_hmfree[BS * HW];
__device__ float g_maxval[BS * HW];
__device__ int   g_argcls[BS * HW];
__device__ int   g_topk_idx[BS * TOPK];
__device__ float g_topk_val[BS * TOPK];
__device__ int   g_topk_cls[BS * TOPK];
__device__ float g_q[BS * NC * C];
__device__ float g_ktop[BS * TOPK * C];
__device__ float g_contrib[BS * NC];

// ---------------------------------------------------------------------------
__global__ void init_kernel() {
    int t = blockIdx.x * blockDim.x + threadIdx.x;
    if (t < BS * NC) { g_peak[t] = -1; g_cmask[t] = 0.f; }
}

// ---------------------------------------------------------------------------
// Scan hm: find peak position per (b,c), class_mask, and per-pixel hm_free.
// Thread handles 4 consecutive pixels (float4). 16*4096 threads.
__global__ void hm_kernel(const float* __restrict__ hm) {
    int t  = blockIdx.x * blockDim.x + threadIdx.x;
    int b  = t >> 12;
    int p4 = (t & 4095) << 2;
    const float* base = hm + (size_t)b * NC * HW + p4;
    float f0 = 1.f, f1 = 1.f, f2 = 1.f, f3 = 1.f;
#pragma unroll 4
    for (int c = 0; c < NC; c++) {
        float4 v = *reinterpret_cast<const float4*>(base + c * HW);
        if (v.x == 1.f) { f0 = 0.f; g_peak[b*NC+c] = p4;     g_cmask[b*NC+c] = 1.f; }
        if (v.y == 1.f) { f1 = 0.f; g_peak[b*NC+c] = p4 + 1; g_cmask[b*NC+c] = 1.f; }
        if (v.z == 1.f) { f2 = 0.f; g_peak[b*NC+c] = p4 + 2; g_cmask[b*NC+c] = 1.f; }
        if (v.w == 1.f) { f3 = 0.f; g_peak[b*NC+c] = p4 + 3; g_cmask[b*NC+c] = 1.f; }
    }
    *reinterpret_cast<float4*>(&g_hmfree[b * HW + p4]) = make_float4(f0, f1, f2, f3);
}

// ---------------------------------------------------------------------------
// Masked per-pixel max/argmax over classes. First-max semantics (strict >).
__global__ void score_kernel(const float* __restrict__ score) {
    __shared__ float scm[NC];
    int b  = blockIdx.x >> 4;
    int p4 = ((((blockIdx.x & 15) << 8) + threadIdx.x)) << 2;
    if (threadIdx.x < NC) scm[threadIdx.x] = g_cmask[b * NC + threadIdx.x];
    __syncthreads();
    float4 hf = *reinterpret_cast<const float4*>(&g_hmfree[b * HW + p4]);
    const float* base = score + (size_t)b * NC * HW + p4;
    float m0 = 0.f, m1 = 0.f, m2 = 0.f, m3 = 0.f;
    int   c0 = 0,   c1 = 0,   c2 = 0,   c3 = 0;
#pragma unroll 4
    for (int c = 0; c < NC; c++) {
        float cm = scm[c];
        float4 v = *reinterpret_cast<const float4*>(base + c * HW);
        float s0 = v.x * cm * hf.x; if (s0 > m0) { m0 = s0; c0 = c; }
        float s1 = v.y * cm * hf.y; if (s1 > m1) { m1 = s1; c1 = c; }
        float s2 = v.z * cm * hf.z; if (s2 > m2) { m2 = s2; c2 = c; }
        float s3 = v.w * cm * hf.w; if (s3 > m3) { m3 = s3; c3 = c; }
    }
    *reinterpret_cast<float4*>(&g_maxval[b * HW + p4]) = make_float4(m0, m1, m2, m3);
    *reinterpret_cast<int4*>(&g_argcls[b * HW + p4])   = make_int4(c0, c1, c2, c3);
}

// ---------------------------------------------------------------------------
// Exact top-128 per batch: binary search threshold on float bit pattern
// (all values >= 0 so uint order == float order), then deterministic
// scan-based compaction. One block (1024 thr) per batch; 16 values/thread.
__global__ void topk_kernel() {
    const int b = blockIdx.x;
    const int tid = threadIdx.x, lane = tid & 31, wid = tid >> 5;
    const unsigned* mv = reinterpret_cast<const unsigned*>(g_maxval) + b * HW;
    unsigned v[16];
#pragma unroll
    for (int i = 0; i < 16; i++) v[i] = mv[i * 1024 + tid];

    __shared__ int s_warp[32];
    __shared__ int s_tot;

    auto blockCount = [&](unsigned thr, bool strict) -> int {
        __syncthreads();
        int c = 0;
#pragma unroll
        for (int i = 0; i < 16; i++) c += strict ? (v[i] > thr) : (v[i] >= thr);
        for (int o = 16; o; o >>= 1) c += __shfl_xor_sync(0xffffffffu, c, o);
        if (lane == 0) s_warp[wid] = c;
        __syncthreads();
        if (tid < 32) {
            int t2 = s_warp[tid];
            for (int o = 16; o; o >>= 1) t2 += __shfl_xor_sync(0xffffffffu, t2, o);
            if (tid == 0) s_tot = t2;
        }
        __syncthreads();
        return s_tot;
    };

    auto blockScanExcl = [&](int x) -> int {
        __syncthreads();
        int incl = x;
        for (int o = 1; o < 32; o <<= 1) {
            int t2 = __shfl_up_sync(0xffffffffu, incl, o);
            if (lane >= o) incl += t2;
        }
        if (lane == 31) s_warp[wid] = incl;
        __syncthreads();
        if (tid < 32) {
            int t2 = s_warp[tid];
            int inc2 = t2;
            for (int o = 1; o < 32; o <<= 1) {
                int u = __shfl_up_sync(0xffffffffu, inc2, o);
                if (tid >= o) inc2 += u;
            }
            s_warp[tid] = inc2 - t2;   // exclusive warp offsets
        }
        __syncthreads();
        return s_warp[wid] + incl - x;
    };

    // Find V = 128th largest value (as uint). Values in [0,1).
    unsigned lo = 0, hi = 0x3F800000u;
    while (lo < hi) {
        unsigned mid = lo + ((hi - lo + 1) >> 1);
        int c = blockCount(mid, false);
        if (c >= TOPK) lo = mid; else hi = mid - 1;
    }
    unsigned V = lo;
    int G  = blockCount(V, true);    // strictly greater count (< 128)
    int En = TOPK - G;               // needed among == V

    // Compact > V (deterministic order: thread-major, then local index)
    int cgt = 0;
#pragma unroll
    for (int i = 0; i < 16; i++) cgt += (v[i] > V);
    int base = blockScanExcl(cgt);
    int slot = base;
#pragma unroll
    for (int i = 0; i < 16; i++) {
        if (v[i] > V) {
            int idx = i * 1024 + tid;
            g_topk_val[b * TOPK + slot] = __uint_as_float(v[i]);
            g_topk_idx[b * TOPK + slot] = idx;
            g_topk_cls[b * TOPK + slot] = g_argcls[b * HW + idx];
            slot++;
        }
    }
    // Fill remaining with == V entries (first En in deterministic order)
    int ceq = 0;
#pragma unroll
    for (int i = 0; i < 16; i++) ceq += (v[i] == V);
    int base2 = blockScanExcl(ceq);
    int r = base2;
#pragma unroll
    for (int i = 0; i < 16; i++) {
        if (v[i] == V) {
            if (r < En) {
                int idx = i * 1024 + tid;
                int s2 = G + r;
                g_topk_val[b * TOPK + s2] = __uint_as_float(v[i]);
                g_topk_idx[b * TOPK + s2] = idx;
                g_topk_cls[b * TOPK + s2] = g_argcls[b * HW + idx];
            }
            r++;
        }
    }
}

// ---------------------------------------------------------------------------
// Gather + L2-normalize feat at peaks (-> q, == k0) and topk pixels (-> ktop).
// One warp per slot; lane handles channels lane and lane+32.
__global__ void gather_kernel(const float* __restrict__ feat) {
    int gw   = (blockIdx.x * blockDim.x + threadIdx.x) >> 5;
    int lane = threadIdx.x & 31;
    if (gw >= BS * NKEY) return;
    int b = gw / NKEY, s = gw % NKEY;
    float* dst;
    int p;
    if (s < NC) {
        p   = g_peak[b * NC + s];
        dst = g_q + (b * NC + s) * C;
        if (p < 0) { dst[lane] = 0.f; dst[lane + 32] = 0.f; return; }
    } else {
        int j = s - NC;
        p   = g_topk_idx[b * TOPK + j];
        dst = g_ktop + (b * TOPK + j) * C;
    }
    const float* fp = feat + (size_t)b * C * HW + p;
    float a  = fp[(size_t)lane * HW];
    float b2 = fp[(size_t)(lane + 32) * HW];
    float ss = a * a + b2 * b2;
#pragma unroll
    for (int o = 16; o; o >>= 1) ss += __shfl_xor_sync(0xffffffffu, ss, o);
    float inv = 1.f / fmaxf(sqrtf(ss), 1e-12f);
    dst[lane]      = a  * inv;
    dst[lane + 32] = b2 * inv;
}

// ---------------------------------------------------------------------------
__global__ void scatter_kernel(float* __restrict__ out) {
    int t = blockIdx.x * blockDim.x + threadIdx.x;
    if (t >= BS * TOPK) return;
    if (g_topk_val[t] > 0.f) {
        int b = t >> 7;
        out[1 + ((size_t)(b * NC + g_topk_cls[t])) * HW + g_topk_idx[t]] = 0.9f;
    }
}

// ---------------------------------------------------------------------------
// Contrastive loss. Block = (batch, group of 8 classes). Keys staged in SMEM
// in two chunks (128 ktop rows, then 80 q rows == k0) so static SMEM < 48KB.
// log(sim_j / sim_sum) = d_j/tau - log(sim_sum).
__global__ void loss_kernel() {
    __shared__ float ks[TOPK * C];      // 32 KB (reused for both chunks)
    __shared__ float qs[8 * C];         // 2 KB
    __shared__ float r_s[8], r_d[8], r_n[8];
    __shared__ float acc_s[8], acc_d[8], acc_n[8];
    int b   = blockIdx.x / 10;
    int ng  = blockIdx.x % 10;          // classes [ng*8, ng*8+8)
    int tid = threadIdx.x, lane = tid & 31, wid = tid >> 5;

    const float* qb = g_q + b * NC * C;
    for (int i = tid; i < 8 * C; i += 256) qs[i] = qb[ng * 8 * C + i];

    // ---- chunk A: 128 topk keys ----
    const float* kt = g_ktop + b * TOPK * C;
    for (int i = tid; i < TOPK * C; i += 256) ks[i] = kt[i];
    float mallA = 0.f, kvalA = 0.f; int kclsA = -1;
    if (tid < TOPK) {
        kvalA = g_topk_val[b * TOPK + tid];
        mallA = (kvalA > 0.f) ? 1.f : 0.f;
        kclsA = g_topk_cls[b * TOPK + tid];
    }
    __syncthreads();
    for (int nl = 0; nl < 8; nl++) {
        int n = ng * 8 + nl;
        float ssum = 0.f, dsum = 0.f, num = 0.f;
        if (tid < TOPK) {
            float d = 0.f;
            const float* kr = ks + tid * C;
            const float* qr = qs + nl * C;
#pragma unroll
            for (int c = 0; c < C; c++) {
                int cc = (c + tid) & (C - 1);
                d += kr[cc] * qr[cc];
            }
            float dt = d / 0.07f;
            float mm = (kclsA == n && kvalA > 0.f) ? 1.f : 0.f;
            ssum = expf(dt) * mallA;
            dsum = dt * mm;
            num  = mm;
        }
        for (int o = 16; o; o >>= 1) {
            ssum += __shfl_xor_sync(0xffffffffu, ssum, o);
            dsum += __shfl_xor_sync(0xffffffffu, dsum, o);
            num  += __shfl_xor_sync(0xffffffffu, num,  o);
        }
        if (lane == 0) { r_s[wid] = ssum; r_d[wid] = dsum; r_n[wid] = num; }
        __syncthreads();
        if (tid == 0) {
            float S = 0.f, D = 0.f, N = 0.f;
            for (int w = 0; w < 8; w++) { S += r_s[w]; D += r_d[w]; N += r_n[w]; }
            acc_s[nl] = S; acc_d[nl] = D; acc_n[nl] = N;
        }
        __syncthreads();
    }

    // ---- chunk B: 80 k0 keys (== q rows) ----
    for (int i = tid; i < NC * C; i += 256) ks[i] = qb[i];
    float mallB = 0.f;
    if (tid < NC) mallB = g_cmask[b * NC + tid];
    __syncthreads();
    for (int nl = 0; nl < 8; nl++) {
        int n = ng * 8 + nl;
        float cm = g_cmask[b * NC + n];
        float ssum = 0.f, dsum = 0.f, num = 0.f;
        if (tid < NC) {
            float d = 0.f;
            const float* kr = ks + tid * C;
            const float* qr = qs + nl * C;
#pragma unroll
            for (int c = 0; c < C; c++) {
                int cc = (c + tid) & (C - 1);
                d += kr[cc] * qr[cc];
            }
            float dt = d / 0.07f;
            float mm = (tid == n) ? cm : 0.f;   // k0_mask diagonal
            ssum = expf(dt) * mallB;
            dsum = dt * mm;
            num  = mm;
        }
        for (int o = 16; o; o >>= 1) {
            ssum += __shfl_xor_sync(0xffffffffu, ssum, o);
            dsum += __shfl_xor_sync(0xffffffffu, dsum, o);
            num  += __shfl_xor_sync(0xffffffffu, num,  o);
        }
        if (lane == 0) { r_s[wid] = ssum; r_d[wid] = dsum; r_n[wid] = num; }
        __syncthreads();
        if (tid == 0) {
            float S = acc_s[nl], D = acc_d[nl], N = acc_n[nl];
            for (int w = 0; w < 8; w++) { S += r_s[w]; D += r_d[w]; N += r_n[w]; }
            float outv = 0.f;
            if (cm != 0.f) outv = (D - N * logf(S)) / N;  // N >= 1 (diagonal)
            g_contrib[b * NC + n] = outv;
        }
        __syncthreads();
    }
}

// ---------------------------------------------------------------------------
__global__ void final_kernel(float* __restrict__ out) {
    __shared__ float rs[8], rc[8];
    int tid = threadIdx.x, lane = tid & 31, wid = tid >> 5;
    float s = 0.f, c = 0.f;
    for (int i = tid; i < BS * NC; i += 256) { s += g_contrib[i]; c += g_cmask[i]; }
    for (int o = 16; o; o >>= 1) {
        s += __shfl_xor_sync(0xffffffffu, s, o);
        c += __shfl_xor_sync(0xffffffffu, c, o);
    }
    if (lane == 0) { rs[wid] = s; rc[wid] = c; }
    __syncthreads();
    if (tid == 0) {
        float S = 0.f, Cc = 0.f;
        for (int w = 0; w < 8; w++) { S += rs[w]; Cc += rc[w]; }
        out[0] = -(S / Cc);
    }
}

// ---------------------------------------------------------------------------
extern "C" void kernel_launch(void* const* d_in, const int* in_sizes, int n_in,
                              void* d_out, int out_size) {
    const float* feat  = (const float*)d_in[0];
    const float* score = (const float*)d_in[1];
    const float* hm    = (const float*)d_in[2];
    float* out = (float*)d_out;

    // Output layout: [ -loss (1 float), pseudo_hm (16*80*128*128 floats) ]
    cudaMemsetAsync(d_out, 0, (size_t)out_size * sizeof(float), 0);

    init_kernel<<<(BS * NC + 255) / 256, 256>>>();
    hm_kernel<<<BS * (HW / 4) / 256, 256>>>(hm);
    score_kernel<<<BS * 16, 256>>>(score);
    topk_kernel<<<BS, 1024>>>();
    gather_kernel<<<(BS * NKEY * 32 + 255) / 256, 256>>>(feat);
    scatter_kernel<<<(BS * TOPK + 255) / 256, 256>>>(out);
    loss_kernel<<<BS * 10, 256>>>();
    final_kernel<<<1, 256>>>(out);
}

// round 3
// speedup vs baseline: 1.1231x; 1.1231x over previous
#include <cuda_runtime.h>
#include <cuda_bf16.h>
#include <cstdint>
#include <math.h>

// Problem constants
constexpr int BS = 16, C = 64, H = 128, W = 128;
constexpr int HW = H * W;           // 16384
constexpr int NC = 80;
constexpr int TOPK = 128;
constexpr int NKEY = TOPK + NC;     // 208

// Scratch (device globals; no allocation allowed)
__device__ int   g_peak[BS * NC];
__device__ float g_cmask[BS * NC];
__device__ float g_hmfree[BS * HW];
__device__ float g_maxval[BS * HW];
__device__ int   g_argcls[BS * HW];
__device__ int   g_topk_idx[BS * TOPK];
__device__ float g_topk_val[BS * TOPK];
__device__ int   g_topk_cls[BS * TOPK];
__device__ float g_q[BS * NC * C];
__device__ float g_ktop[BS * TOPK * C];
__device__ float g_contrib[BS * NC];

// ---------------------------------------------------------------------------
__global__ void init_kernel() {
    int t = blockIdx.x * blockDim.x + threadIdx.x;
    if (t < BS * NC) { g_peak[t] = -1; g_cmask[t] = 0.f; }
}

// ---------------------------------------------------------------------------
// Scan hm: find peak position per (b,c), class_mask, and per-pixel hm_free.
// Thread handles 4 consecutive pixels (float4); 8-deep prefetch for MLP.
__global__ void hm_kernel(const float* __restrict__ hm) {
    int t  = blockIdx.x * blockDim.x + threadIdx.x;
    int b  = t >> 12;
    int p4 = (t & 4095) << 2;
    const float* base = hm + (size_t)b * NC * HW + p4;
    float f0 = 1.f, f1 = 1.f, f2 = 1.f, f3 = 1.f;
#pragma unroll
    for (int cc = 0; cc < NC; cc += 8) {
        float4 r[8];
#pragma unroll
        for (int j = 0; j < 8; j++)
            r[j] = *reinterpret_cast<const float4*>(base + (cc + j) * HW);
#pragma unroll
        for (int j = 0; j < 8; j++) {
            int c = cc + j;
            if (r[j].x == 1.f) { f0 = 0.f; g_peak[b*NC+c] = p4;     g_cmask[b*NC+c] = 1.f; }
            if (r[j].y == 1.f) { f1 = 0.f; g_peak[b*NC+c] = p4 + 1; g_cmask[b*NC+c] = 1.f; }
            if (r[j].z == 1.f) { f2 = 0.f; g_peak[b*NC+c] = p4 + 2; g_cmask[b*NC+c] = 1.f; }
            if (r[j].w == 1.f) { f3 = 0.f; g_peak[b*NC+c] = p4 + 3; g_cmask[b*NC+c] = 1.f; }
        }
    }
    *reinterpret_cast<float4*>(&g_hmfree[b * HW + p4]) = make_float4(f0, f1, f2, f3);
}

// ---------------------------------------------------------------------------
// Masked per-pixel max/argmax over classes. First-max semantics (strict >).
// 8-deep float4 prefetch for MLP.
__global__ void score_kernel(const float* __restrict__ score) {
    __shared__ float scm[NC];
    int b  = blockIdx.x >> 4;
    int p4 = ((((blockIdx.x & 15) << 8) + threadIdx.x)) << 2;
    if (threadIdx.x < NC) scm[threadIdx.x] = g_cmask[b * NC + threadIdx.x];
    __syncthreads();
    float4 hf = *reinterpret_cast<const float4*>(&g_hmfree[b * HW + p4]);
    const float* base = score + (size_t)b * NC * HW + p4;
    float m0 = 0.f, m1 = 0.f, m2 = 0.f, m3 = 0.f;
    int   c0 = 0,   c1 = 0,   c2 = 0,   c3 = 0;
#pragma unroll
    for (int cc = 0; cc < NC; cc += 8) {
        float4 r[8];
#pragma unroll
        for (int j = 0; j < 8; j++)
            r[j] = *reinterpret_cast<const float4*>(base + (cc + j) * HW);
#pragma unroll
        for (int j = 0; j < 8; j++) {
            int c = cc + j;
            float cm = scm[c];
            float s0 = r[j].x * cm * hf.x; if (s0 > m0) { m0 = s0; c0 = c; }
            float s1 = r[j].y * cm * hf.y; if (s1 > m1) { m1 = s1; c1 = c; }
            float s2 = r[j].z * cm * hf.z; if (s2 > m2) { m2 = s2; c2 = c; }
            float s3 = r[j].w * cm * hf.w; if (s3 > m3) { m3 = s3; c3 = c; }
        }
    }
    *reinterpret_cast<float4*>(&g_maxval[b * HW + p4]) = make_float4(m0, m1, m2, m3);
    *reinterpret_cast<int4*>(&g_argcls[b * HW + p4])   = make_int4(c0, c1, c2, c3);
}

// ---------------------------------------------------------------------------
// Exact top-128 per batch: binary search threshold on float bit pattern
// (all values >= 0 so uint order == float order), then deterministic
// scan-based compaction. One block (512 thr) per batch; 32 values/thread.
// ONE barrier per search iteration: warp shuffle-reduce -> lane0 atomicAdd
// into a per-iteration slot -> single __syncthreads -> all read total.
__global__ void topk_kernel() {
    const int b = blockIdx.x;
    const int tid = threadIdx.x, lane = tid & 31, wid = tid >> 5;  // 16 warps
    const unsigned* mv = reinterpret_cast<const unsigned*>(g_maxval) + b * HW;
    unsigned v[32];
#pragma unroll
    for (int i = 0; i < 32; i++) v[i] = mv[i * 512 + tid];

    __shared__ int s_cnt[34];
    __shared__ int s_warp[16];
    for (int i = tid; i < 34; i += 512) s_cnt[i] = 0;
    __syncthreads();

    // Find V = 128th largest value (as uint). Values in [0,1).
    unsigned lo = 0, hi = 0x3F800000u;
    int it = 0;
    while (lo < hi) {
        unsigned mid = lo + ((hi - lo + 1) >> 1);
        int c = 0;
#pragma unroll
        for (int i = 0; i < 32; i++) c += (v[i] >= mid);
#pragma unroll
        for (int o = 16; o; o >>= 1) c += __shfl_xor_sync(0xffffffffu, c, o);
        if (lane == 0) atomicAdd(&s_cnt[it], c);
        __syncthreads();
        int tot = s_cnt[it];
        it++;
        if (tot >= TOPK) lo = mid; else hi = mid - 1;
    }
    unsigned V = lo;

    // Strictly-greater count G (slot 33)
    {
        int c = 0;
#pragma unroll
        for (int i = 0; i < 32; i++) c += (v[i] > V);
#pragma unroll
        for (int o = 16; o; o >>= 1) c += __shfl_xor_sync(0xffffffffu, c, o);
        if (lane == 0) atomicAdd(&s_cnt[33], c);
        __syncthreads();
    }
    int G  = s_cnt[33];
    int En = TOPK - G;               // needed among == V

    auto scanExcl = [&](int x) -> int {
        __syncthreads();
        int incl = x;
#pragma unroll
        for (int o = 1; o < 32; o <<= 1) {
            int t2 = __shfl_up_sync(0xffffffffu, incl, o);
            if (lane >= o) incl += t2;
        }
        if (lane == 31) s_warp[wid] = incl;
        __syncthreads();
        if (tid < 16) {
            int t2 = s_warp[tid];
            int inc2 = t2;
#pragma unroll
            for (int o = 1; o < 16; o <<= 1) {
                int u = __shfl_up_sync(0x0000ffffu, inc2, o);
                if (tid >= o) inc2 += u;
            }
            s_warp[tid] = inc2 - t2;   // exclusive warp offsets
        }
        __syncthreads();
        return s_warp[wid] + incl - x;
    };

    // Compact > V (deterministic order: reg index major, then tid)
    int cgt = 0;
#pragma unroll
    for (int i = 0; i < 32; i++) cgt += (v[i] > V);
    int slot = scanExcl(cgt);
#pragma unroll
    for (int i = 0; i < 32; i++) {
        if (v[i] > V) {
            int idx = i * 512 + tid;
            g_topk_val[b * TOPK + slot] = __uint_as_float(v[i]);
            g_topk_idx[b * TOPK + slot] = idx;
            g_topk_cls[b * TOPK + slot] = g_argcls[b * HW + idx];
            slot++;
        }
    }
    // Fill remaining with == V entries (first En in deterministic order)
    int ceq = 0;
#pragma unroll
    for (int i = 0; i < 32; i++) ceq += (v[i] == V);
    int r = scanExcl(ceq);
#pragma unroll
    for (int i = 0; i < 32; i++) {
        if (v[i] == V) {
            if (r < En) {
                int idx = i * 512 + tid;
                int s2 = G + r;
                g_topk_val[b * TOPK + s2] = __uint_as_float(v[i]);
                g_topk_idx[b * TOPK + s2] = idx;
                g_topk_cls[b * TOPK + s2] = g_argcls[b * HW + idx];
            }
            r++;
        }
    }
}

// ---------------------------------------------------------------------------
// Gather + L2-normalize feat at peaks (-> q, == k0) and topk pixels (-> ktop).
// One warp per slot; lane handles channels lane and lane+32.
// Also fuses the pseudo_hm scatter (lane 0 of topk slots writes 0.9).
__global__ void gather_kernel(const float* __restrict__ feat, float* __restrict__ out) {
    int gw   = (blockIdx.x * blockDim.x + threadIdx.x) >> 5;
    int lane = threadIdx.x & 31;
    if (gw >= BS * NKEY) return;
    int b = gw / NKEY, s = gw % NKEY;
    float* dst;
    int p;
    if (s < NC) {
        p   = g_peak[b * NC + s];
        dst = g_q + (b * NC + s) * C;
        if (p < 0) { dst[lane] = 0.f; dst[lane + 32] = 0.f; return; }
    } else {
        int j = s - NC;
        p   = g_topk_idx[b * TOPK + j];
        dst = g_ktop + (b * TOPK + j) * C;
        if (lane == 0 && g_topk_val[b * TOPK + j] > 0.f) {
            out[1 + ((size_t)(b * NC + g_topk_cls[b * TOPK + j])) * HW + p] = 0.9f;
        }
    }
    const float* fp = feat + (size_t)b * C * HW + p;
    float a  = fp[(size_t)lane * HW];
    float b2 = fp[(size_t)(lane + 32) * HW];
    float ss = a * a + b2 * b2;
#pragma unroll
    for (int o = 16; o; o >>= 1) ss += __shfl_xor_sync(0xffffffffu, ss, o);
    float inv = 1.f / fmaxf(sqrtf(ss), 1e-12f);
    dst[lane]      = a  * inv;
    dst[lane + 32] = b2 * inv;
}

// ---------------------------------------------------------------------------
// Contrastive loss. Block = (batch, group of 8 classes). Keys staged in SMEM
// in two chunks (128 ktop rows, then 80 q rows == k0) so static SMEM < 48KB.
// log(sim_j / sim_sum) = d_j/tau - log(sim_sum).
__global__ void loss_kernel() {
    __shared__ float ks[TOPK * C];      // 32 KB (reused for both chunks)
    __shared__ float qs[8 * C];         // 2 KB
    __shared__ float r_s[8], r_d[8], r_n[8];
    __shared__ float acc_s[8], acc_d[8], acc_n[8];
    int b   = blockIdx.x / 10;
    int ng  = blockIdx.x % 10;          // classes [ng*8, ng*8+8)
    int tid = threadIdx.x, lane = tid & 31, wid = tid >> 5;

    const float* qb = g_q + b * NC * C;
    for (int i = tid; i < 8 * C; i += 256) qs[i] = qb[ng * 8 * C + i];

    // ---- chunk A: 128 topk keys ----
    const float* kt = g_ktop + b * TOPK * C;
    for (int i = tid; i < TOPK * C; i += 256) ks[i] = kt[i];
    float mallA = 0.f, kvalA = 0.f; int kclsA = -1;
    if (tid < TOPK) {
        kvalA = g_topk_val[b * TOPK + tid];
        mallA = (kvalA > 0.f) ? 1.f : 0.f;
        kclsA = g_topk_cls[b * TOPK + tid];
    }
    __syncthreads();
    for (int nl = 0; nl < 8; nl++) {
        int n = ng * 8 + nl;
        float ssum = 0.f, dsum = 0.f, num = 0.f;
        if (tid < TOPK) {
            float d = 0.f;
            const float* kr = ks + tid * C;
            const float* qr = qs + nl * C;
#pragma unroll
            for (int c = 0; c < C; c++) {
                int cc = (c + tid) & (C - 1);
                d += kr[cc] * qr[cc];
            }
            float dt = d / 0.07f;
            float mm = (kclsA == n && kvalA > 0.f) ? 1.f : 0.f;
            ssum = expf(dt) * mallA;
            dsum = dt * mm;
            num  = mm;
        }
        for (int o = 16; o; o >>= 1) {
            ssum += __shfl_xor_sync(0xffffffffu, ssum, o);
            dsum += __shfl_xor_sync(0xffffffffu, dsum, o);
            num  += __shfl_xor_sync(0xffffffffu, num,  o);
        }
        if (lane == 0) { r_s[wid] = ssum; r_d[wid] = dsum; r_n[wid] = num; }
        __syncthreads();
        if (tid == 0) {
            float S = 0.f, D = 0.f, N = 0.f;
            for (int w = 0; w < 8; w++) { S += r_s[w]; D += r_d[w]; N += r_n[w]; }
            acc_s[nl] = S; acc_d[nl] = D; acc_n[nl] = N;
        }
        __syncthreads();
    }

    // ---- chunk B: 80 k0 keys (== q rows) ----
    for (int i = tid; i < NC * C; i += 256) ks[i] = qb[i];
    float mallB = 0.f;
    if (tid < NC) mallB = g_cmask[b * NC + tid];
    __syncthreads();
    for (int nl = 0; nl < 8; nl++) {
        int n = ng * 8 + nl;
        float cm = g_cmask[b * NC + n];
        float ssum = 0.f, dsum = 0.f, num = 0.f;
        if (tid < NC) {
            float d = 0.f;
            const float* kr = ks + tid * C;
            const float* qr = qs + nl * C;
#pragma unroll
            for (int c = 0; c < C; c++) {
                int cc = (c + tid) & (C - 1);
                d += kr[cc] * qr[cc];
            }
            float dt = d / 0.07f;
            float mm = (tid == n) ? cm : 0.f;   // k0_mask diagonal
            ssum = expf(dt) * mallB;
            dsum = dt * mm;
            num  = mm;
        }
        for (int o = 16; o; o >>= 1) {
            ssum += __shfl_xor_sync(0xffffffffu, ssum, o);
            dsum += __shfl_xor_sync(0xffffffffu, dsum, o);
            num  += __shfl_xor_sync(0xffffffffu, num,  o);
        }
        if (lane == 0) { r_s[wid] = ssum; r_d[wid] = dsum; r_n[wid] = num; }
        __syncthreads();
        if (tid == 0) {
            float S = acc_s[nl], D = acc_d[nl], N = acc_n[nl];
            for (int w = 0; w < 8; w++) { S += r_s[w]; D += r_d[w]; N += r_n[w]; }
            float outv = 0.f;
            if (cm != 0.f) outv = (D - N * logf(S)) / N;  // N >= 1 (diagonal)
            g_contrib[b * NC + n] = outv;
        }
        __syncthreads();
    }
}

// ---------------------------------------------------------------------------
__global__ void final_kernel(float* __restrict__ out) {
    __shared__ float rs[8], rc[8];
    int tid = threadIdx.x, lane = tid & 31, wid = tid >> 5;
    float s = 0.f, c = 0.f;
    for (int i = tid; i < BS * NC; i += 256) { s += g_contrib[i]; c += g_cmask[i]; }
    for (int o = 16; o; o >>= 1) {
        s += __shfl_xor_sync(0xffffffffu, s, o);
        c += __shfl_xor_sync(0xffffffffu, c, o);
    }
    if (lane == 0) { rs[wid] = s; rc[wid] = c; }
    __syncthreads();
    if (tid == 0) {
        float S = 0.f, Cc = 0.f;
        for (int w = 0; w < 8; w++) { S += rs[w]; Cc += rc[w]; }
        out[0] = -(S / Cc);
    }
}

// ---------------------------------------------------------------------------
extern "C" void kernel_launch(void* const* d_in, const int* in_sizes, int n_in,
                              void* d_out, int out_size) {
    const float* feat  = (const float*)d_in[0];
    const float* score = (const float*)d_in[1];
    const float* hm    = (const float*)d_in[2];
    float* out = (float*)d_out;

    // Output layout: [ -loss (1 float), pseudo_hm (16*80*128*128 floats) ]
    cudaMemsetAsync(d_out, 0, (size_t)out_size * sizeof(float), 0);

    init_kernel<<<(BS * NC + 255) / 256, 256>>>();
    hm_kernel<<<BS * (HW / 4) / 256, 256>>>(hm);
    score_kernel<<<BS * 16, 256>>>(score);
    topk_kernel<<<BS, 512>>>();
    gather_kernel<<<(BS * NKEY * 32 + 255) / 256, 256>>>(feat, out);
    loss_kernel<<<BS * 10, 256>>>();
    final_kernel<<<1, 256>>>(out);
}